// round 11
// baseline (speedup 1.0000x reference)
#include <cuda_runtime.h>
#include <cstdint>

// StateObsMLP via mma.sync tf32 (baseline PTX, works at compute_103).
//   obs_emb  = obs(512)   @ obs_W(512x256)        + obs_b
//   state_emb= relu(state(64) @ state_W[c](64x256) + state_b[c])
//   out      = concat(state_emb, obs_emb)(512) @ l2_W[c](512x256) + l2_b[c]
//
// R11: 32-row tiles, 512 threads (16 warps). Warp w = m-block (w/8),
// n-range 32*(w%8). Same per-warp chunk work as R10 but 2x warps/SM to
// hide sync+LDS+MMA latency, and each weight chunk serves 32 rows (L2
// traffic halved).

#define CATS   32
#define EMB    256
#define B_MAX  2048
#define MT     32
#define KC     32
#define NTH    512
#define ASTR   36            // A smem row stride: banks (4*gid+tig)%32 unique
#define WSTR   264           // W smem row stride: banks (8*tig+gid)%32 unique
#define XSTR   516           // x smem row stride: conflict-free A-frag reads
#define MAX_TILES 128
#define NCTAS  96

__device__ int g_perm[B_MAX];
__device__ int g_cat_start[CATS + 1];
__device__ int g_tiles[MAX_TILES];
__device__ int g_ntiles;

// ---------------------------------------------------------------------------
// Kernel 1: bin rows by category + flattened (cat, 32-row tile) worklist.
// ---------------------------------------------------------------------------
__global__ void bin_kernel(const int* __restrict__ cat, int B) {
    __shared__ int cnt[CATS];
    __shared__ int st[CATS + 1];
    __shared__ int cur[CATS];
    int t = threadIdx.x;
    if (t < CATS) cnt[t] = 0;
    __syncthreads();
    for (int b = t; b < B; b += blockDim.x) atomicAdd(&cnt[cat[b]], 1);
    __syncthreads();
    if (t == 0) {
        int s = 0;
        for (int c = 0; c < CATS; c++) { st[c] = s; s += cnt[c]; }
        st[CATS] = s;
        int n = 0;
        for (int c = 0; c < CATS; c++) {
            int nt = (cnt[c] + MT - 1) / MT;
            for (int i = 0; i < nt; i++) g_tiles[n++] = (c << 16) | i;
        }
        g_ntiles = n;
    }
    __syncthreads();
    if (t < CATS) cur[t] = st[t];
    __syncthreads();
    for (int b = t; b < B; b += blockDim.x) {
        int pos = atomicAdd(&cur[cat[b]], 1);
        g_perm[pos] = b;
    }
    if (t <= CATS) g_cat_start[t] = st[t];
}

// ---------------------------------------------------------------------------
// mma.sync helpers
// ---------------------------------------------------------------------------
__device__ __forceinline__ uint32_t f2tf(float f) {
    uint32_t u;
    asm("cvt.rna.tf32.f32 %0, %1;" : "=r"(u) : "f"(f));
    return u;
}
__device__ __forceinline__ void mma_tf32(float* c,
    uint32_t a0, uint32_t a1, uint32_t a2, uint32_t a3,
    uint32_t b0, uint32_t b1)
{
    asm volatile(
        "mma.sync.aligned.m16n8k8.row.col.f32.tf32.tf32.f32 "
        "{%0,%1,%2,%3}, {%4,%5,%6,%7}, {%8,%9}, {%0,%1,%2,%3};"
        : "+f"(c[0]), "+f"(c[1]), "+f"(c[2]), "+f"(c[3])
        : "r"(a0), "r"(a1), "r"(a2), "r"(a3), "r"(b0), "r"(b1));
}
__device__ __forceinline__ uint32_t smem_u32(const void* p) {
    uint32_t a;
    asm("{ .reg .u64 t; cvta.to.shared.u64 t, %1; cvt.u32.u64 %0, t; }"
        : "=r"(a) : "l"(p));
    return a;
}
#define CP16(dst, src, sz) \
    asm volatile("cp.async.cg.shared.global [%0], [%1], 16, %2;" \
                 :: "r"(dst), "l"(src), "r"(sz))

// One 32-K chunk of MMAs. Abase: this warp's m-block row0 at chunk k-offset.
__device__ __forceinline__ void chunk_mma(
    const float* __restrict__ Abase, int astride,
    const float* __restrict__ Wbuf,
    int gid, int tig, int nbase, float c[16])
{
    #pragma unroll
    for (int ks = 0; ks < 4; ks++) {
        int k0 = ks * 8;
        uint32_t a0 = f2tf(Abase[gid * astride + k0 + tig]);
        uint32_t a1 = f2tf(Abase[(gid + 8) * astride + k0 + tig]);
        uint32_t a2 = f2tf(Abase[gid * astride + k0 + tig + 4]);
        uint32_t a3 = f2tf(Abase[(gid + 8) * astride + k0 + tig + 4]);
        #pragma unroll
        for (int nt = 0; nt < 4; nt++) {
            int nb = nbase + nt * 8;
            uint32_t b0 = f2tf(Wbuf[(k0 + tig) * WSTR + nb + gid]);
            uint32_t b1 = f2tf(Wbuf[(k0 + tig + 4) * WSTR + nb + gid]);
            mma_tf32(c + nt * 4, a0, a1, a2, a3, b0, b1);
        }
    }
}

// ---------------------------------------------------------------------------
// Kernel 2: fused per (category, 32-row tile), persistent over worklist.
// smem floats: a_s 2*32*36 =2304 | w_s 2*32*264 =16896 | x_s 32*516 =16512
// total 35712 floats = 142848 B (1 CTA/SM).
// ---------------------------------------------------------------------------
#define SMEM_FLOATS (2 * MT * ASTR + 2 * KC * WSTR + MT * XSTR)

__global__ __launch_bounds__(NTH, 1)
void fused_kernel(const float* __restrict__ state,
                  const float* __restrict__ obs,
                  const float* __restrict__ obs_W,
                  const float* __restrict__ obs_b,
                  const float* __restrict__ state_W,
                  const float* __restrict__ state_b,
                  const float* __restrict__ l2_W,
                  const float* __restrict__ l2_b,
                  float* __restrict__ out)
{
    extern __shared__ float sm[];
    float* a_s = sm;                       // 2 buffers of MT*ASTR
    float* w_s = a_s + 2 * MT * ASTR;      // 2 buffers of KC*WSTR
    float* x_s = w_s + 2 * KC * WSTR;      // MT x XSTR
    __shared__ int rows_sh[MT];

    int t    = threadIdx.x;
    int lane = t & 31;
    int wid  = t >> 5;
    int gid  = lane >> 2;       // row within m16 block
    int tig  = lane & 3;
    int wg   = wid >> 3;        // m-block (0 or 1): tile rows [16*wg, 16*wg+16)
    int nbase = (wid & 7) * 32; // warp's n range

    int mrow = wg * 16;         // this warp's m-block base row within tile

    uint32_t a_u[2] = { smem_u32(a_s), smem_u32(a_s + MT * ASTR) };
    uint32_t w_u[2] = { smem_u32(w_s), smem_u32(w_s + KC * WSTR) };

    int NT = g_ntiles;
    for (int widx = blockIdx.x; widx < NT; widx += gridDim.x) {
        __syncthreads();
        int ent  = g_tiles[widx];
        int g    = ent >> 16;
        int tile = ent & 0xFFFF;
        int start = g_cat_start[g];
        int cnt   = g_cat_start[g + 1] - start;
        if (t < MT)
            rows_sh[t] = (tile * MT + t < cnt) ? g_perm[start + tile * MT + t] : -1;
        __syncthreads();

        float c[16];

        // ---- copies: W chunk = 32x256 = 2048 float4; A = 32 rows x 8 f4 ----
        #define COPY_W(Wp, ch, buf) do { \
            const float* _src = (Wp) + (size_t)(ch) * KC * EMB; \
            _Pragma("unroll") \
            for (int i = t; i < 2048; i += NTH) { \
                int k = i >> 6, q = i & 63; \
                CP16(w_u[buf] + (uint32_t)(k * WSTR + q * 4) * 4, \
                     _src + k * EMB + q * 4, 16); \
            } } while (0)
        #define COPY_A(Ap, lda, ch, buf) do { \
            if (t < 256) { \
                int row = t >> 3, q = t & 7; \
                int rg = rows_sh[row]; \
                const float* _src = (Ap) + (size_t)(rg < 0 ? 0 : rg) * (lda) \
                                  + (ch) * KC + q * 4; \
                CP16(a_u[buf] + (uint32_t)(row * ASTR + q * 4) * 4, _src, \
                     rg < 0 ? 0u : 16u); \
            } } while (0)

        #define PHASE_GMEM(Ap, lda, Wp, nch) do { \
            COPY_A(Ap, lda, 0, 0); COPY_W(Wp, 0, 0); \
            asm volatile("cp.async.commit_group;"); \
            for (int ch = 0; ch < (nch); ch++) { \
                int pb = ch & 1; \
                if (ch + 1 < (nch)) { \
                    COPY_A(Ap, lda, ch + 1, pb ^ 1); \
                    COPY_W(Wp, ch + 1, pb ^ 1); \
                    asm volatile("cp.async.commit_group;"); \
                    asm volatile("cp.async.wait_group 1;"); \
                } else asm volatile("cp.async.wait_group 0;"); \
                __syncthreads(); \
                chunk_mma(a_s + pb * (MT * ASTR) + mrow * ASTR, ASTR, \
                          w_s + pb * (KC * WSTR), gid, tig, nbase, c); \
                __syncthreads(); \
            } } while (0)

        #define PHASE_SMEM(Wp, nch) do { \
            COPY_W(Wp, 0, 0); \
            asm volatile("cp.async.commit_group;"); \
            for (int ch = 0; ch < (nch); ch++) { \
                int pb = ch & 1; \
                if (ch + 1 < (nch)) { \
                    COPY_W(Wp, ch + 1, pb ^ 1); \
                    asm volatile("cp.async.commit_group;"); \
                    asm volatile("cp.async.wait_group 1;"); \
                } else asm volatile("cp.async.wait_group 0;"); \
                __syncthreads(); \
                chunk_mma(x_s + ch * KC + mrow * XSTR, XSTR, \
                          w_s + pb * (KC * WSTR), gid, tig, nbase, c); \
                __syncthreads(); \
            } } while (0)

        // --- Phase A: state_emb = relu(state @ state_W[g] + state_b[g]) ---
        #pragma unroll
        for (int i = 0; i < 16; i++) c[i] = 0.f;
        PHASE_GMEM(state, 64, state_W + (size_t)g * 64 * EMB, 2);
        {
            const float* bs = state_b + (size_t)g * EMB;
            #pragma unroll
            for (int nt = 0; nt < 4; nt++) {
                int nb = nbase + nt * 8 + 2 * tig;
                float2 bb = *(const float2*)(bs + nb);
                float2 v0, v1;
                v0.x = fmaxf(c[nt * 4 + 0] + bb.x, 0.f);
                v0.y = fmaxf(c[nt * 4 + 1] + bb.y, 0.f);
                v1.x = fmaxf(c[nt * 4 + 2] + bb.x, 0.f);
                v1.y = fmaxf(c[nt * 4 + 3] + bb.y, 0.f);
                *(float2*)(x_s + (mrow + gid) * XSTR + nb)       = v0;
                *(float2*)(x_s + (mrow + gid + 8) * XSTR + nb)   = v1;
            }
        }
        __syncthreads();

        // --- Phase B: obs_emb = obs @ obs_W + obs_b -> x cols [256,512) ---
        #pragma unroll
        for (int i = 0; i < 16; i++) c[i] = 0.f;
        PHASE_GMEM(obs, 512, obs_W, 16);
        {
            #pragma unroll
            for (int nt = 0; nt < 4; nt++) {
                int nb = nbase + nt * 8 + 2 * tig;
                float2 bb = *(const float2*)(obs_b + nb);
                float2 v0, v1;
                v0.x = c[nt * 4 + 0] + bb.x;
                v0.y = c[nt * 4 + 1] + bb.y;
                v1.x = c[nt * 4 + 2] + bb.x;
                v1.y = c[nt * 4 + 3] + bb.y;
                *(float2*)(x_s + (mrow + gid) * XSTR + 256 + nb)     = v0;
                *(float2*)(x_s + (mrow + gid + 8) * XSTR + 256 + nb) = v1;
            }
        }
        __syncthreads();

        // --- Phase C: out = x @ l2_W[g] + l2_b[g], scatter rows ---
        #pragma unroll
        for (int i = 0; i < 16; i++) c[i] = 0.f;
        PHASE_SMEM(l2_W + (size_t)g * 512 * EMB, 16);
        {
            const float* bl = l2_b + (size_t)g * EMB;
            int rg0 = rows_sh[mrow + gid];
            int rg1 = rows_sh[mrow + gid + 8];
            #pragma unroll
            for (int nt = 0; nt < 4; nt++) {
                int nb = nbase + nt * 8 + 2 * tig;
                float2 bb = *(const float2*)(bl + nb);
                if (rg0 >= 0) {
                    float2 v;
                    v.x = c[nt * 4 + 0] + bb.x;
                    v.y = c[nt * 4 + 1] + bb.y;
                    *(float2*)(out + (size_t)rg0 * EMB + nb) = v;
                }
                if (rg1 >= 0) {
                    float2 v;
                    v.x = c[nt * 4 + 2] + bb.x;
                    v.y = c[nt * 4 + 3] + bb.y;
                    *(float2*)(out + (size_t)rg1 * EMB + nb) = v;
                }
            }
        }
    }
}

// ---------------------------------------------------------------------------
extern "C" void kernel_launch(void* const* d_in, const int* in_sizes, int n_in,
                              void* d_out, int out_size) {
    const float* state   = (const float*)d_in[0];
    const float* obs     = (const float*)d_in[1];
    const int*   cat_ids = (const int*)  d_in[2];
    const float* obs_W   = (const float*)d_in[3];
    const float* obs_b   = (const float*)d_in[4];
    const float* state_W = (const float*)d_in[5];
    const float* state_b = (const float*)d_in[6];
    const float* l2_W    = (const float*)d_in[7];
    const float* l2_b    = (const float*)d_in[8];
    float* out = (float*)d_out;

    int B = in_sizes[2];

    size_t smem_bytes = SMEM_FLOATS * sizeof(float);   // 142848
    cudaFuncSetAttribute(fused_kernel,
                         cudaFuncAttributeMaxDynamicSharedMemorySize,
                         (int)smem_bytes);

    bin_kernel<<<1, 256>>>(cat_ids, B);
    fused_kernel<<<NCTAS, NTH, smem_bytes>>>(
        state, obs, obs_W, obs_b, state_W, state_b, l2_W, l2_b, out);
}

// round 12
// speedup vs baseline: 1.0752x; 1.0752x over previous
#include <cuda_runtime.h>
#include <cstdint>

// StateObsMLP via mma.sync tf32 (baseline PTX, works at compute_103).
// R12: MT=16 tiles (136 tiles -> full chip) x 16 warps (n=16 per warp);
// weights pre-converted to tf32 bits (kills B-side cvt); x stored
// pre-converted (kills phase-C A-side cvt).

#define CATS   32
#define EMB    256
#define B_MAX  2048
#define MT     16
#define KC     32
#define NTH    512
#define ASTR   36            // A smem row stride: banks (4*gid+tig)%32 unique
#define WSTR   264           // W smem row stride: banks (8*tig+gid)%32 unique
#define XSTR   516           // x smem row stride: conflict-free A-frag reads
#define MAX_TILES (CATS + B_MAX / MT)
#define NCTAS  148

__device__ int g_perm[B_MAX];
__device__ int g_cat_start[CATS + 1];
__device__ int g_tiles[MAX_TILES];
__device__ int g_ntiles;

// Pre-converted (tf32-rounded) weights
__device__ float g_obsWc[512 * 256];
__device__ float g_stateWc[CATS * 64 * 256];
__device__ float g_l2Wc[CATS * 512 * 256];

// ---------------------------------------------------------------------------
__device__ __forceinline__ uint32_t f2tf(float f) {
    uint32_t u;
    asm("cvt.rna.tf32.f32 %0, %1;" : "=r"(u) : "f"(f));
    return u;
}

// Kernel 0: round all weights to tf32 once.
__global__ void cvt_kernel(const float4* __restrict__ obs_W,
                           const float4* __restrict__ state_W,
                           const float4* __restrict__ l2_W)
{
    const int N_OBS = 512 * 256 / 4;                  // 32768
    const int N_ST  = CATS * 64 * 256 / 4;            // 131072
    const int N_L2  = CATS * 512 * 256 / 4;           // 1048576
    int total = N_OBS + N_ST + N_L2;
    for (int i = blockIdx.x * blockDim.x + threadIdx.x; i < total;
         i += gridDim.x * blockDim.x) {
        const float4* src; float4* dst; int j;
        if (i < N_OBS)             { src = obs_W;   dst = (float4*)g_obsWc;   j = i; }
        else if (i < N_OBS + N_ST) { src = state_W; dst = (float4*)g_stateWc; j = i - N_OBS; }
        else                       { src = l2_W;    dst = (float4*)g_l2Wc;    j = i - N_OBS - N_ST; }
        float4 v = src[j];
        v.x = __uint_as_float(f2tf(v.x));
        v.y = __uint_as_float(f2tf(v.y));
        v.z = __uint_as_float(f2tf(v.z));
        v.w = __uint_as_float(f2tf(v.w));
        dst[j] = v;
    }
}

// ---------------------------------------------------------------------------
// Kernel 1: bin rows by category + flattened (cat, 16-row tile) worklist.
// ---------------------------------------------------------------------------
__global__ void bin_kernel(const int* __restrict__ cat, int B) {
    __shared__ int cnt[CATS];
    __shared__ int st[CATS + 1];
    __shared__ int cur[CATS];
    int t = threadIdx.x;
    if (t < CATS) cnt[t] = 0;
    __syncthreads();
    for (int b = t; b < B; b += blockDim.x) atomicAdd(&cnt[cat[b]], 1);
    __syncthreads();
    if (t == 0) {
        int s = 0;
        for (int c = 0; c < CATS; c++) { st[c] = s; s += cnt[c]; }
        st[CATS] = s;
        int n = 0;
        for (int c = 0; c < CATS; c++) {
            int nt = (cnt[c] + MT - 1) / MT;
            for (int i = 0; i < nt; i++) g_tiles[n++] = (c << 16) | i;
        }
        g_ntiles = n;
    }
    __syncthreads();
    if (t < CATS) cur[t] = st[t];
    __syncthreads();
    for (int b = t; b < B; b += blockDim.x) {
        int pos = atomicAdd(&cur[cat[b]], 1);
        g_perm[pos] = b;
    }
    if (t <= CATS) g_cat_start[t] = st[t];
}

// ---------------------------------------------------------------------------
__device__ __forceinline__ void mma_tf32(float* c,
    uint32_t a0, uint32_t a1, uint32_t a2, uint32_t a3,
    uint32_t b0, uint32_t b1)
{
    asm volatile(
        "mma.sync.aligned.m16n8k8.row.col.f32.tf32.tf32.f32 "
        "{%0,%1,%2,%3}, {%4,%5,%6,%7}, {%8,%9}, {%0,%1,%2,%3};"
        : "+f"(c[0]), "+f"(c[1]), "+f"(c[2]), "+f"(c[3])
        : "r"(a0), "r"(a1), "r"(a2), "r"(a3), "r"(b0), "r"(b1));
}
__device__ __forceinline__ uint32_t smem_u32(const void* p) {
    uint32_t a;
    asm("{ .reg .u64 t; cvta.to.shared.u64 t, %1; cvt.u32.u64 %0, t; }"
        : "=r"(a) : "l"(p));
    return a;
}
#define CP16(dst, src, sz) \
    asm volatile("cp.async.cg.shared.global [%0], [%1], 16, %2;" \
                 :: "r"(dst), "l"(src), "r"(sz))

// One 32-K chunk: n=16 per warp (2 n-tiles), c[8].
// CVTA: whether A elements need tf32 rounding (raw inputs) or are pre-rounded.
// W buffers always hold pre-rounded bits -> plain reinterpret.
template <bool CVTA>
__device__ __forceinline__ void chunk_mma(
    const float* __restrict__ Abase, int astride,
    const float* __restrict__ Wbuf,
    int gid, int tig, int nbase, float c[8])
{
    #pragma unroll
    for (int ks = 0; ks < 4; ks++) {
        int k0 = ks * 8;
        uint32_t a0, a1, a2, a3;
        if (CVTA) {
            a0 = f2tf(Abase[gid * astride + k0 + tig]);
            a1 = f2tf(Abase[(gid + 8) * astride + k0 + tig]);
            a2 = f2tf(Abase[gid * astride + k0 + tig + 4]);
            a3 = f2tf(Abase[(gid + 8) * astride + k0 + tig + 4]);
        } else {
            a0 = __float_as_uint(Abase[gid * astride + k0 + tig]);
            a1 = __float_as_uint(Abase[(gid + 8) * astride + k0 + tig]);
            a2 = __float_as_uint(Abase[gid * astride + k0 + tig + 4]);
            a3 = __float_as_uint(Abase[(gid + 8) * astride + k0 + tig + 4]);
        }
        #pragma unroll
        for (int nt = 0; nt < 2; nt++) {
            int nb = nbase + nt * 8;
            uint32_t b0 = __float_as_uint(Wbuf[(k0 + tig) * WSTR + nb + gid]);
            uint32_t b1 = __float_as_uint(Wbuf[(k0 + tig + 4) * WSTR + nb + gid]);
            mma_tf32(c + nt * 4, a0, a1, a2, a3, b0, b1);
        }
    }
}

// ---------------------------------------------------------------------------
// Kernel 2: fused per (category, 16-row tile), 512 threads (16 warps,
// warp w -> n in [16w, 16w+16)), persistent over worklist.
// smem floats: a_s 2*16*36=1152 | w_s 2*32*264=16896 | x_s 16*516=8256
// total 26304 floats = 105216 B.
// ---------------------------------------------------------------------------
#define SMEM_FLOATS (2 * MT * ASTR + 2 * KC * WSTR + MT * XSTR)

__global__ __launch_bounds__(NTH, 1)
void fused_kernel(const float* __restrict__ state,
                  const float* __restrict__ obs,
                  const float* __restrict__ obs_b,
                  const float* __restrict__ state_b,
                  const float* __restrict__ l2_b,
                  float* __restrict__ out)
{
    extern __shared__ float sm[];
    float* a_s = sm;                       // 2 buffers of MT*ASTR
    float* w_s = a_s + 2 * MT * ASTR;      // 2 buffers of KC*WSTR
    float* x_s = w_s + 2 * KC * WSTR;      // MT x XSTR (pre-converted bits)
    __shared__ int rows_sh[MT];

    int t    = threadIdx.x;
    int lane = t & 31;
    int wid  = t >> 5;
    int gid  = lane >> 2;       // row within m16
    int tig  = lane & 3;
    int nbase = wid * 16;       // warp's n range [nbase, nbase+16)

    uint32_t a_u[2] = { smem_u32(a_s), smem_u32(a_s + MT * ASTR) };
    uint32_t w_u[2] = { smem_u32(w_s), smem_u32(w_s + KC * WSTR) };

    int NT = g_ntiles;
    for (int widx = blockIdx.x; widx < NT; widx += gridDim.x) {
        __syncthreads();
        int ent  = g_tiles[widx];
        int g    = ent >> 16;
        int tile = ent & 0xFFFF;
        int start = g_cat_start[g];
        int cnt   = g_cat_start[g + 1] - start;
        if (t < MT)
            rows_sh[t] = (tile * MT + t < cnt) ? g_perm[start + tile * MT + t] : -1;
        __syncthreads();

        float c[8];

        #define COPY_W(Wp, ch, buf) do { \
            const float* _src = (Wp) + (size_t)(ch) * KC * EMB; \
            _Pragma("unroll") \
            for (int i = t; i < 2048; i += NTH) { \
                int k = i >> 6, q = i & 63; \
                CP16(w_u[buf] + (uint32_t)(k * WSTR + q * 4) * 4, \
                     _src + k * EMB + q * 4, 16); \
            } } while (0)
        #define COPY_A(Ap, lda, ch, buf) do { \
            if (t < 128) { \
                int row = t >> 3, q = t & 7; \
                int rg = rows_sh[row]; \
                const float* _src = (Ap) + (size_t)(rg < 0 ? 0 : rg) * (lda) \
                                  + (ch) * KC + q * 4; \
                CP16(a_u[buf] + (uint32_t)(row * ASTR + q * 4) * 4, _src, \
                     rg < 0 ? 0u : 16u); \
            } } while (0)

        #define PHASE_GMEM(Ap, lda, Wp, nch) do { \
            COPY_A(Ap, lda, 0, 0); COPY_W(Wp, 0, 0); \
            asm volatile("cp.async.commit_group;"); \
            for (int ch = 0; ch < (nch); ch++) { \
                int pb = ch & 1; \
                if (ch + 1 < (nch)) { \
                    COPY_A(Ap, lda, ch + 1, pb ^ 1); \
                    COPY_W(Wp, ch + 1, pb ^ 1); \
                    asm volatile("cp.async.commit_group;"); \
                    asm volatile("cp.async.wait_group 1;"); \
                } else asm volatile("cp.async.wait_group 0;"); \
                __syncthreads(); \
                chunk_mma<true>(a_s + pb * (MT * ASTR), ASTR, \
                                w_s + pb * (KC * WSTR), gid, tig, nbase, c); \
                __syncthreads(); \
            } } while (0)

        #define PHASE_SMEM(Wp, nch) do { \
            COPY_W(Wp, 0, 0); \
            asm volatile("cp.async.commit_group;"); \
            for (int ch = 0; ch < (nch); ch++) { \
                int pb = ch & 1; \
                if (ch + 1 < (nch)) { \
                    COPY_W(Wp, ch + 1, pb ^ 1); \
                    asm volatile("cp.async.commit_group;"); \
                    asm volatile("cp.async.wait_group 1;"); \
                } else asm volatile("cp.async.wait_group 0;"); \
                __syncthreads(); \
                chunk_mma<false>(x_s + ch * KC, XSTR, \
                                 w_s + pb * (KC * WSTR), gid, tig, nbase, c); \
                __syncthreads(); \
            } } while (0)

        // --- Phase A: state_emb = relu(state @ state_W[g] + state_b[g]) ---
        #pragma unroll
        for (int i = 0; i < 8; i++) c[i] = 0.f;
        PHASE_GMEM(state, 64, g_stateWc + (size_t)g * 64 * EMB, 2);
        {
            const float* bs = state_b + (size_t)g * EMB;
            #pragma unroll
            for (int nt = 0; nt < 2; nt++) {
                int nb = nbase + nt * 8 + 2 * tig;
                float2 bb = *(const float2*)(bs + nb);
                float2 v0, v1;
                v0.x = __uint_as_float(f2tf(fmaxf(c[nt * 4 + 0] + bb.x, 0.f)));
                v0.y = __uint_as_float(f2tf(fmaxf(c[nt * 4 + 1] + bb.y, 0.f)));
                v1.x = __uint_as_float(f2tf(fmaxf(c[nt * 4 + 2] + bb.x, 0.f)));
                v1.y = __uint_as_float(f2tf(fmaxf(c[nt * 4 + 3] + bb.y, 0.f)));
                *(float2*)(x_s + gid * XSTR + nb)       = v0;
                *(float2*)(x_s + (gid + 8) * XSTR + nb) = v1;
            }
        }
        __syncthreads();

        // --- Phase B: obs_emb = obs @ obs_W + obs_b -> x cols [256,512) ---
        #pragma unroll
        for (int i = 0; i < 8; i++) c[i] = 0.f;
        PHASE_GMEM(obs, 512, g_obsWc, 16);
        {
            #pragma unroll
            for (int nt = 0; nt < 2; nt++) {
                int nb = nbase + nt * 8 + 2 * tig;
                float2 bb = *(const float2*)(obs_b + nb);
                float2 v0, v1;
                v0.x = __uint_as_float(f2tf(c[nt * 4 + 0] + bb.x));
                v0.y = __uint_as_float(f2tf(c[nt * 4 + 1] + bb.y));
                v1.x = __uint_as_float(f2tf(c[nt * 4 + 2] + bb.x));
                v1.y = __uint_as_float(f2tf(c[nt * 4 + 3] + bb.y));
                *(float2*)(x_s + gid * XSTR + 256 + nb)       = v0;
                *(float2*)(x_s + (gid + 8) * XSTR + 256 + nb) = v1;
            }
        }
        __syncthreads();

        // --- Phase C: out = x @ l2_W[g] + l2_b[g], scatter rows ---
        #pragma unroll
        for (int i = 0; i < 8; i++) c[i] = 0.f;
        PHASE_SMEM(g_l2Wc + (size_t)g * 512 * EMB, 16);
        {
            const float* bl = l2_b + (size_t)g * EMB;
            int rg0 = rows_sh[gid];
            int rg1 = rows_sh[gid + 8];
            #pragma unroll
            for (int nt = 0; nt < 2; nt++) {
                int nb = nbase + nt * 8 + 2 * tig;
                float2 bb = *(const float2*)(bl + nb);
                if (rg0 >= 0) {
                    float2 v;
                    v.x = c[nt * 4 + 0] + bb.x;
                    v.y = c[nt * 4 + 1] + bb.y;
                    *(float2*)(out + (size_t)rg0 * EMB + nb) = v;
                }
                if (rg1 >= 0) {
                    float2 v;
                    v.x = c[nt * 4 + 2] + bb.x;
                    v.y = c[nt * 4 + 3] + bb.y;
                    *(float2*)(out + (size_t)rg1 * EMB + nb) = v;
                }
            }
        }
    }
}

// ---------------------------------------------------------------------------
extern "C" void kernel_launch(void* const* d_in, const int* in_sizes, int n_in,
                              void* d_out, int out_size) {
    const float* state   = (const float*)d_in[0];
    const float* obs     = (const float*)d_in[1];
    const int*   cat_ids = (const int*)  d_in[2];
    const float* obs_W   = (const float*)d_in[3];
    const float* obs_b   = (const float*)d_in[4];
    const float* state_W = (const float*)d_in[5];
    const float* state_b = (const float*)d_in[6];
    const float* l2_W    = (const float*)d_in[7];
    const float* l2_b    = (const float*)d_in[8];
    float* out = (float*)d_out;

    int B = in_sizes[2];

    size_t smem_bytes = SMEM_FLOATS * sizeof(float);   // 105216
    cudaFuncSetAttribute(fused_kernel,
                         cudaFuncAttributeMaxDynamicSharedMemorySize,
                         (int)smem_bytes);

    cvt_kernel<<<1184, 512>>>((const float4*)obs_W, (const float4*)state_W,
                              (const float4*)l2_W);
    bin_kernel<<<1, 256>>>(cat_ids, B);
    fused_kernel<<<NCTAS, NTH, smem_bytes>>>(
        state, obs, obs_b, state_b, l2_b, out);
}

// round 14
// speedup vs baseline: 1.1635x; 1.0822x over previous
#include <cuda_runtime.h>
#include <cstdint>

// StateObsMLP via mma.sync tf32 (baseline PTX, works at compute_103).
// R14 = R13 with the nullptr-arithmetic compile fix:
// MT=16 x 16 warps (n=16/warp, 136 tiles -> full chip);
// NO weight pre-convert pass (cvt hidden in-loop under smem floor);
// 3-deep buffers -> ONE __syncthreads per chunk; prefetch before MMA.

#define CATS   32
#define EMB    256
#define B_MAX  2048
#define MT     16
#define KC     32
#define NTH    512
#define ASTR   36            // A smem row stride: banks 4*gid+tig unique
#define WSTR   264           // W smem row stride: banks 8*tig+gid unique
#define XSTR   516           // x smem row stride: banks 4*gid+tig unique
#define ABUF   (MT * ASTR)   // 576 floats
#define WBUF   (KC * WSTR)   // 8448 floats
#define MAX_TILES (CATS + B_MAX / MT)
#define NCTAS  148

__device__ int g_perm[B_MAX];
__device__ int g_cat_start[CATS + 1];
__device__ int g_tiles[MAX_TILES];
__device__ int g_ntiles;

// ---------------------------------------------------------------------------
// Kernel 1: bin rows by category + flattened (cat, 16-row tile) worklist.
// ---------------------------------------------------------------------------
__global__ void bin_kernel(const int* __restrict__ cat, int B) {
    __shared__ int cnt[CATS];
    __shared__ int st[CATS + 1];
    __shared__ int cur[CATS];
    int t = threadIdx.x;
    if (t < CATS) cnt[t] = 0;
    __syncthreads();
    for (int b = t; b < B; b += blockDim.x) atomicAdd(&cnt[cat[b]], 1);
    __syncthreads();
    if (t == 0) {
        int s = 0;
        for (int c = 0; c < CATS; c++) { st[c] = s; s += cnt[c]; }
        st[CATS] = s;
        int n = 0;
        for (int c = 0; c < CATS; c++) {
            int nt = (cnt[c] + MT - 1) / MT;
            for (int i = 0; i < nt; i++) g_tiles[n++] = (c << 16) | i;
        }
        g_ntiles = n;
    }
    __syncthreads();
    if (t < CATS) cur[t] = st[t];
    __syncthreads();
    for (int b = t; b < B; b += blockDim.x) {
        int pos = atomicAdd(&cur[cat[b]], 1);
        g_perm[pos] = b;
    }
    if (t <= CATS) g_cat_start[t] = st[t];
}

// ---------------------------------------------------------------------------
// mma.sync helpers
// ---------------------------------------------------------------------------
__device__ __forceinline__ uint32_t f2tf(float f) {
    uint32_t u;
    asm("cvt.rna.tf32.f32 %0, %1;" : "=r"(u) : "f"(f));
    return u;
}
__device__ __forceinline__ void mma_tf32(float* c,
    uint32_t a0, uint32_t a1, uint32_t a2, uint32_t a3,
    uint32_t b0, uint32_t b1)
{
    asm volatile(
        "mma.sync.aligned.m16n8k8.row.col.f32.tf32.tf32.f32 "
        "{%0,%1,%2,%3}, {%4,%5,%6,%7}, {%8,%9}, {%0,%1,%2,%3};"
        : "+f"(c[0]), "+f"(c[1]), "+f"(c[2]), "+f"(c[3])
        : "r"(a0), "r"(a1), "r"(a2), "r"(a3), "r"(b0), "r"(b1));
}
__device__ __forceinline__ uint32_t smem_u32(const void* p) {
    uint32_t a;
    asm("{ .reg .u64 t; cvta.to.shared.u64 t, %1; cvt.u32.u64 %0, t; }"
        : "=r"(a) : "l"(p));
    return a;
}
#define CP16(dst, src, sz) \
    asm volatile("cp.async.cg.shared.global [%0], [%1], 16, %2;" \
                 :: "r"(dst), "l"(src), "r"(sz))

// One 32-K chunk: n=16 per warp (2 n-tiles), c[8]. B always cvt'd in-loop
// (hidden under smem floor). CVTA: A needs rounding (raw inputs) or is
// pre-rounded (x_s written rounded at epilogues).
template <bool CVTA>
__device__ __forceinline__ void chunk_mma(
    const float* __restrict__ Abase, int astride,
    const float* __restrict__ Wbuf,
    int gid, int tig, int nbase, float c[8])
{
    #pragma unroll
    for (int ks = 0; ks < 4; ks++) {
        int k0 = ks * 8;
        uint32_t a0, a1, a2, a3;
        if (CVTA) {
            a0 = f2tf(Abase[gid * astride + k0 + tig]);
            a1 = f2tf(Abase[(gid + 8) * astride + k0 + tig]);
            a2 = f2tf(Abase[gid * astride + k0 + tig + 4]);
            a3 = f2tf(Abase[(gid + 8) * astride + k0 + tig + 4]);
        } else {
            a0 = __float_as_uint(Abase[gid * astride + k0 + tig]);
            a1 = __float_as_uint(Abase[(gid + 8) * astride + k0 + tig]);
            a2 = __float_as_uint(Abase[gid * astride + k0 + tig + 4]);
            a3 = __float_as_uint(Abase[(gid + 8) * astride + k0 + tig + 4]);
        }
        #pragma unroll
        for (int nt = 0; nt < 2; nt++) {
            int nb = nbase + nt * 8;
            uint32_t b0 = f2tf(Wbuf[(k0 + tig) * WSTR + nb + gid]);
            uint32_t b1 = f2tf(Wbuf[(k0 + tig + 4) * WSTR + nb + gid]);
            mma_tf32(c + nt * 4, a0, a1, a2, a3, b0, b1);
        }
    }
}

// ---------------------------------------------------------------------------
// Kernel 2: fused per (category, 16-row tile), 512 threads (16 warps,
// warp w -> n in [16w,16w+16)), persistent over worklist.
// smem floats: a_s 3*576 | w_s 3*8448 | x_s 16*516  = 35328 fl = 141312 B.
// ---------------------------------------------------------------------------
#define SMEM_FLOATS (3 * ABUF + 3 * WBUF + MT * XSTR)

__global__ __launch_bounds__(NTH, 1)
void fused_kernel(const float* __restrict__ state,
                  const float* __restrict__ obs,
                  const float* __restrict__ obs_W,
                  const float* __restrict__ obs_b,
                  const float* __restrict__ state_W,
                  const float* __restrict__ state_b,
                  const float* __restrict__ l2_W,
                  const float* __restrict__ l2_b,
                  float* __restrict__ out)
{
    extern __shared__ float sm[];
    float* a_s = sm;                 // 3 buffers of ABUF
    float* w_s = a_s + 3 * ABUF;     // 3 buffers of WBUF
    float* x_s = w_s + 3 * WBUF;     // MT x XSTR (pre-rounded tf32 bits)
    __shared__ int rows_sh[MT];

    int t    = threadIdx.x;
    int lane = t & 31;
    int wid  = t >> 5;
    int gid  = lane >> 2;       // row within m16
    int tig  = lane & 3;
    int nbase = wid * 16;       // warp's n range [nbase, nbase+16)

    uint32_t a_u = smem_u32(a_s);
    uint32_t w_u = smem_u32(w_s);

    int NT = g_ntiles;
    for (int widx = blockIdx.x; widx < NT; widx += gridDim.x) {
        __syncthreads();            // protect rows_sh / x_s from prev tile
        int ent  = g_tiles[widx];
        int g    = ent >> 16;
        int tile = ent & 0xFFFF;
        int start = g_cat_start[g];
        int cnt   = g_cat_start[g + 1] - start;
        if (t < MT)
            rows_sh[t] = (tile * MT + t < cnt) ? g_perm[start + tile * MT + t] : -1;
        __syncthreads();

        float c[8];

        #define COPY_W(Wp, ch, buf) do { \
            const float* _src = (Wp) + (size_t)(ch) * KC * EMB; \
            _Pragma("unroll") \
            for (int i = t; i < 2048; i += NTH) { \
                int k = i >> 6, q = i & 63; \
                CP16(w_u + (uint32_t)((buf) * WBUF + k * WSTR + q * 4) * 4, \
                     _src + k * EMB + q * 4, 16); \
            } } while (0)
        #define COPY_A(Ap, lda, ch, buf) do { \
            if (t < 128) { \
                int row = t >> 3, q = t & 7; \
                int rg = rows_sh[row]; \
                const float* _src = (Ap) + (size_t)(rg < 0 ? 0 : rg) * (lda) \
                                  + (ch) * KC + q * 4; \
                CP16(a_u + (uint32_t)((buf) * ABUF + row * ASTR + q * 4) * 4, \
                     _src, rg < 0 ? 0u : 16u); \
            } } while (0)

        // 3-buffer, depth-2 prefetch, ONE barrier per chunk.
        // HASA is a compile-time literal 0/1; Ap must be a valid pointer
        // even when HASA==0 (expansion is type-checked).
        #define PHASE(Ap, lda, HASA, Wp, nch, AV, astride, CVTA_) do { \
            if (HASA) COPY_A(Ap, lda, 0, 0); \
            COPY_W(Wp, 0, 0); \
            asm volatile("cp.async.commit_group;"); \
            if ((nch) > 1) { \
                if (HASA) COPY_A(Ap, lda, 1, 1); \
                COPY_W(Wp, 1, 1); \
                asm volatile("cp.async.commit_group;"); \
            } \
            for (int ch = 0; ch < (nch); ch++) { \
                if (ch + 1 < (nch)) asm volatile("cp.async.wait_group 1;"); \
                else                asm volatile("cp.async.wait_group 0;"); \
                __syncthreads(); \
                if (ch + 2 < (nch)) { \
                    int nb3 = (ch + 2) % 3; \
                    if (HASA) COPY_A(Ap, lda, ch + 2, nb3); \
                    COPY_W(Wp, ch + 2, nb3); \
                    asm volatile("cp.async.commit_group;"); \
                } \
                chunk_mma<CVTA_>(AV(ch), astride, \
                                 w_s + (ch % 3) * WBUF, gid, tig, nbase, c); \
            } } while (0)

        #define AV_GM(ch) (a_s + ((ch) % 3) * ABUF)
        #define AV_X(ch)  (x_s + (ch) * KC)

        // --- Phase A: state_emb = relu(state @ state_W[g] + state_b[g]) ---
        #pragma unroll
        for (int i = 0; i < 8; i++) c[i] = 0.f;
        PHASE(state, 64, 1, state_W + (size_t)g * 64 * EMB, 2, AV_GM, ASTR, true);
        {
            const float* bs = state_b + (size_t)g * EMB;
            #pragma unroll
            for (int nt = 0; nt < 2; nt++) {
                int nb = nbase + nt * 8 + 2 * tig;
                float2 bb = *(const float2*)(bs + nb);
                float2 v0, v1;
                v0.x = __uint_as_float(f2tf(fmaxf(c[nt * 4 + 0] + bb.x, 0.f)));
                v0.y = __uint_as_float(f2tf(fmaxf(c[nt * 4 + 1] + bb.y, 0.f)));
                v1.x = __uint_as_float(f2tf(fmaxf(c[nt * 4 + 2] + bb.x, 0.f)));
                v1.y = __uint_as_float(f2tf(fmaxf(c[nt * 4 + 3] + bb.y, 0.f)));
                *(float2*)(x_s + gid * XSTR + nb)       = v0;
                *(float2*)(x_s + (gid + 8) * XSTR + nb) = v1;
            }
        }
        __syncthreads();   // x_s[.,0:256) done; buffers free for next phase

        // --- Phase B: obs_emb = obs @ obs_W + obs_b -> x cols [256,512) ---
        #pragma unroll
        for (int i = 0; i < 8; i++) c[i] = 0.f;
        PHASE(obs, 512, 1, obs_W, 16, AV_GM, ASTR, true);
        {
            #pragma unroll
            for (int nt = 0; nt < 2; nt++) {
                int nb = nbase + nt * 8 + 2 * tig;
                float2 bb = *(const float2*)(obs_b + nb);
                float2 v0, v1;
                v0.x = __uint_as_float(f2tf(c[nt * 4 + 0] + bb.x));
                v0.y = __uint_as_float(f2tf(c[nt * 4 + 1] + bb.y));
                v1.x = __uint_as_float(f2tf(c[nt * 4 + 2] + bb.x));
                v1.y = __uint_as_float(f2tf(c[nt * 4 + 3] + bb.y));
                *(float2*)(x_s + gid * XSTR + 256 + nb)       = v0;
                *(float2*)(x_s + (gid + 8) * XSTR + 256 + nb) = v1;
            }
        }
        __syncthreads();   // x_s complete

        // --- Phase C: out = x @ l2_W[g] + l2_b[g], scatter rows ---
        // Pass `state` as the (unused) A pointer: HASA=0 disables COPY_A at
        // runtime but the expansion still type-checks pointer arithmetic.
        #pragma unroll
        for (int i = 0; i < 8; i++) c[i] = 0.f;
        PHASE(state, 64, 0, l2_W + (size_t)g * 512 * EMB, 16, AV_X, XSTR, false);
        {
            const float* bl = l2_b + (size_t)g * EMB;
            int rg0 = rows_sh[gid];
            int rg1 = rows_sh[gid + 8];
            #pragma unroll
            for (int nt = 0; nt < 2; nt++) {
                int nb = nbase + nt * 8 + 2 * tig;
                float2 bb = *(const float2*)(bl + nb);
                if (rg0 >= 0) {
                    float2 v;
                    v.x = c[nt * 4 + 0] + bb.x;
                    v.y = c[nt * 4 + 1] + bb.y;
                    *(float2*)(out + (size_t)rg0 * EMB + nb) = v;
                }
                if (rg1 >= 0) {
                    float2 v;
                    v.x = c[nt * 4 + 2] + bb.x;
                    v.y = c[nt * 4 + 3] + bb.y;
                    *(float2*)(out + (size_t)rg1 * EMB + nb) = v;
                }
            }
        }
    }
}

// ---------------------------------------------------------------------------
extern "C" void kernel_launch(void* const* d_in, const int* in_sizes, int n_in,
                              void* d_out, int out_size) {
    const float* state   = (const float*)d_in[0];
    const float* obs     = (const float*)d_in[1];
    const int*   cat_ids = (const int*)  d_in[2];
    const float* obs_W   = (const float*)d_in[3];
    const float* obs_b   = (const float*)d_in[4];
    const float* state_W = (const float*)d_in[5];
    const float* state_b = (const float*)d_in[6];
    const float* l2_W    = (const float*)d_in[7];
    const float* l2_b    = (const float*)d_in[8];
    float* out = (float*)d_out;

    int B = in_sizes[2];

    size_t smem_bytes = SMEM_FLOATS * sizeof(float);   // 141312
    cudaFuncSetAttribute(fused_kernel,
                         cudaFuncAttributeMaxDynamicSharedMemorySize,
                         (int)smem_bytes);

    bin_kernel<<<1, 1024>>>(cat_ids, B);
    fused_kernel<<<NCTAS, NTH, smem_bytes>>>(
        state, obs, obs_W, obs_b, state_W, state_b, l2_W, l2_b, out);
}